// round 5
// baseline (speedup 1.0000x reference)
#include <cuda_runtime.h>
#include <cuda_bf16.h>
#include <cstdint>

// ---------------------------------------------------------------------------
// GCN VGAE encoder (fp32, f32x2 FFMA, 128x128 SMEM-tiled GEMMs, fused epilogue)
//   dinv = rsqrt(indeg+1)
//   conv: hs = (X@W)*dinv[row]; agg = hs (self-loop seed) + scatter(hs[src]->dst)
//         next-layer input = relu(dinv[row]*agg + b)  <- fused into consumer GEMM
//   heads: [mu|lv] = relu(dinv*aggB + b2) @ [Wmu|Wlv] + bias
// Scratch = __device__ globals, referenced ONLY from device code.
// ---------------------------------------------------------------------------

#define MAXN 50000
#define FDIM 128

__device__ float g_dinv[MAXN];
__device__ float g_hs  [MAXN * FDIM];
__device__ float g_aggA[MAXN * FDIM];
__device__ float g_aggB[MAXN * FDIM];

typedef unsigned long long ull;

#define SPLAT2(d, x) asm("mov.b64 %0, {%1, %1};" : "=l"(d) : "f"(x))
#define FMA2(d, a, b, c) \
    asm("fma.rn.f32x2 %0, %1, %2, %3;" : "=l"(d) : "l"(a), "l"(b), "l"(c))
#define UNPACK2(lo, hi, v) \
    asm("mov.b64 {%0, %1}, %2;" : "=f"(lo), "=f"(hi) : "l"(v))

// ---------------- degree / dinv ----------------

__global__ void init_one_kernel(int N) {
    int i = blockIdx.x * blockDim.x + threadIdx.x;
    if (i < N) g_dinv[i] = 1.0f;
}

__global__ void count_deg_kernel(const int* __restrict__ ei, int E) {
    int e = blockIdx.x * blockDim.x + threadIdx.x;
    if (e < E) atomicAdd(&g_dinv[ei[E + e]], 1.0f);
}

__global__ void rsqrt_kernel(int N) {
    int i = blockIdx.x * blockDim.x + threadIdx.x;
    if (i < N) g_dinv[i] = rsqrtf(g_dinv[i]);
}

// ---------------- GEMM machinery: 128x128 tile, 512 threads ----------------
// Thread (tx,ty): tx = t%16 -> cols tx*8..+7 ; ty = t/16 -> rows ty*4..+3.
// Ws[128][128] (k-major rows), Xs[128 rows][128 k]. 128KB smem, 1 block/SM.

#define GEMM_SMEM (2 * 128 * 128 * 4)

// Stage X tile (128 rows x 128 cols) into smem; optionally relu(dinv*v + bias).
__device__ __forceinline__ void load_xtile(float* Xs, const float* __restrict__ src,
                                           const float* __restrict__ bias, int fuse,
                                           int rowBase, int N, int t) {
#pragma unroll
    for (int i = 0; i < 8; i++) {
        int idx = t + i * 512;          // 0..4095 float4 slots
        int r = idx >> 5, c4 = idx & 31;
        int rg = rowBase + r;
        float4 v = make_float4(0.f, 0.f, 0.f, 0.f);
        if (rg < N) {
            v = ((const float4*)src)[(size_t)rg * 32 + c4];
            if (fuse) {
                float dv = g_dinv[rg];
                float4 bb = ((const float4*)bias)[c4];
                v.x = fmaxf(v.x * dv + bb.x, 0.f);
                v.y = fmaxf(v.y * dv + bb.y, 0.f);
                v.z = fmaxf(v.z * dv + bb.z, 0.f);
                v.w = fmaxf(v.w * dv + bb.w, 0.f);
            }
        }
        ((float4*)Xs)[idx] = v;
    }
}

// 128x128x128 tile product. acc[row][colpair] (4 rows x 4 f32x2 = 8 cols).
__device__ __forceinline__ void mm_tile(const float* Ws, const float* Xs,
                                        int c0, int r0, ull acc[4][4]) {
#pragma unroll
    for (int i = 0; i < 4; i++)
#pragma unroll
        for (int j = 0; j < 4; j++) acc[i][j] = 0ull;

#pragma unroll 2
    for (int k0 = 0; k0 < 128; k0 += 4) {
        float4 a[4];
#pragma unroll
        for (int i = 0; i < 4; i++)
            a[i] = *(const float4*)(Xs + (r0 + i) * 128 + k0);
#pragma unroll
        for (int kk = 0; kk < 4; kk++) {
            ulonglong2 b01 = *(const ulonglong2*)(Ws + (k0 + kk) * 128 + c0);
            ulonglong2 b23 = *(const ulonglong2*)(Ws + (k0 + kk) * 128 + c0 + 4);
#pragma unroll
            for (int i = 0; i < 4; i++) {
                const float* ap = (const float*)&a[i];
                ull s;
                SPLAT2(s, ap[kk]);
                FMA2(acc[i][0], s, b01.x, acc[i][0]);
                FMA2(acc[i][1], s, b01.y, acc[i][1]);
                FMA2(acc[i][2], s, b23.x, acc[i][2]);
                FMA2(acc[i][3], s, b23.y, acc[i][3]);
            }
        }
    }
}

// ---------------- conv GEMM: hs = (X@W)*dinv ; agg seeded = hs -------------
// stage 0: X = xin (raw), agg out = g_aggA
// stage 1: X = relu(dinv*g_aggA + bias), agg out = g_aggB

__global__ void __launch_bounds__(512)
gemm_conv_kernel(const float* __restrict__ xin,
                 const float* __restrict__ W,
                 const float* __restrict__ bias,
                 int N, int stage) {
    extern __shared__ float sm[];
    float* Ws = sm;
    float* Xs = sm + 128 * 128;
    const int t = threadIdx.x;

    const float* src = (stage == 0) ? xin : (const float*)g_aggA;
    float* aggout = (stage == 0) ? g_aggA : g_aggB;

#pragma unroll
    for (int i = 0; i < 8; i++) {
        int idx = t + i * 512;
        ((float4*)Ws)[idx] = ((const float4*)W)[idx];
    }
    const int rowBase = blockIdx.x * 128;
    load_xtile(Xs, src, bias, stage != 0, rowBase, N, t);
    __syncthreads();

    const int tx = t & 15, ty = t >> 4;
    const int c0 = tx * 8, r0 = ty * 4;
    ull acc[4][4];
    mm_tile(Ws, Xs, c0, r0, acc);

#pragma unroll
    for (int i = 0; i < 4; i++) {
        int r = rowBase + r0 + i;
        if (r < N) {
            float dv = g_dinv[r];
            float v[8];
            UNPACK2(v[0], v[1], acc[i][0]);
            UNPACK2(v[2], v[3], acc[i][1]);
            UNPACK2(v[4], v[5], acc[i][2]);
            UNPACK2(v[6], v[7], acc[i][3]);
            float4 o0 = make_float4(v[0] * dv, v[1] * dv, v[2] * dv, v[3] * dv);
            float4 o1 = make_float4(v[4] * dv, v[5] * dv, v[6] * dv, v[7] * dv);
            *(float4*)(g_hs   + (size_t)r * 128 + c0)     = o0;
            *(float4*)(g_hs   + (size_t)r * 128 + c0 + 4) = o1;
            *(float4*)(aggout + (size_t)r * 128 + c0)     = o0;  // self-loop seed
            *(float4*)(aggout + (size_t)r * 128 + c0 + 4) = o1;
        }
    }
}

// ---------------- final GEMM: [mu|lv] = relu(dinv*aggB+b2) @ [Wmu|Wlv] + bias

__global__ void __launch_bounds__(512)
gemm_final_kernel(const float* __restrict__ Wmu,
                  const float* __restrict__ Wlv,
                  const float* __restrict__ bmu,
                  const float* __restrict__ blv,
                  const float* __restrict__ b2,
                  float* __restrict__ out,
                  int N) {
    extern __shared__ float sm[];
    float* Ws = sm;
    float* Xs = sm + 128 * 128;
    const int t = threadIdx.x;

#pragma unroll
    for (int i = 0; i < 8; i++) {
        int idx = t + i * 512;
        int k = idx >> 5;
        int cc4 = idx & 31;
        float4 v = (cc4 < 16) ? ((const float4*)Wmu)[k * 16 + cc4]
                              : ((const float4*)Wlv)[k * 16 + (cc4 - 16)];
        ((float4*)Ws)[idx] = v;
    }
    const int rowBase = blockIdx.x * 128;
    load_xtile(Xs, (const float*)g_aggB, b2, 1, rowBase, N, t);
    __syncthreads();

    const int tx = t & 15, ty = t >> 4;
    const int c0 = tx * 8, r0 = ty * 4;
    ull acc[4][4];
    mm_tile(Ws, Xs, c0, r0, acc);

    const bool is_mu = (c0 < 64);
    const int cl = is_mu ? c0 : (c0 - 64);
    float4 bs0 = is_mu ? *(const float4*)(bmu + cl)     : *(const float4*)(blv + cl);
    float4 bs1 = is_mu ? *(const float4*)(bmu + cl + 4) : *(const float4*)(blv + cl + 4);
#pragma unroll
    for (int i = 0; i < 4; i++) {
        int r = rowBase + r0 + i;
        if (r < N) {
            float v[8];
            UNPACK2(v[0], v[1], acc[i][0]);
            UNPACK2(v[2], v[3], acc[i][1]);
            UNPACK2(v[4], v[5], acc[i][2]);
            UNPACK2(v[6], v[7], acc[i][3]);
            float4 o0 = make_float4(v[0] + bs0.x, v[1] + bs0.y, v[2] + bs0.z, v[3] + bs0.w);
            float4 o1 = make_float4(v[4] + bs1.x, v[5] + bs1.y, v[6] + bs1.z, v[7] + bs1.w);
            float* base = is_mu ? (out + (size_t)r * 64 + cl)
                                : (out + (size_t)N * 64 + (size_t)r * 64 + cl);
            *(float4*)(base)     = o0;
            *(float4*)(base + 4) = o1;
        }
    }
}

// ---------------- scatter: agg[dst] += hs[src] (one warp per edge) ----------

__device__ __forceinline__ void red_add_v4(float* p, float4 v) {
    asm volatile("red.global.add.v4.f32 [%0], {%1, %2, %3, %4};"
                 :: "l"(p), "f"(v.x), "f"(v.y), "f"(v.z), "f"(v.w)
                 : "memory");
}

__global__ void scatter_kernel(const int* __restrict__ ei, int E, int which) {
    int w = (blockIdx.x * blockDim.x + threadIdx.x) >> 5;
    int lane = threadIdx.x & 31;
    if (w >= E) return;
    float* agg = which ? g_aggB : g_aggA;
    int s = ei[w];
    int d = ei[E + w];
    float4 v = *(const float4*)(g_hs + (size_t)s * 128 + lane * 4);
    red_add_v4(agg + (size_t)d * 128 + lane * 4, v);
}

// ---------------- launch ----------------

extern "C" void kernel_launch(void* const* d_in, const int* in_sizes, int n_in,
                              void* d_out, int out_size) {
    const float* x   = (const float*)d_in[0];
    const int*   ei  = (const int*)d_in[1];      // int32 edge_index [2, E]
    const float* W1  = (const float*)d_in[2];
    const float* b1  = (const float*)d_in[3];
    const float* W2  = (const float*)d_in[4];
    const float* b2  = (const float*)d_in[5];
    const float* Wmu = (const float*)d_in[6];
    const float* bmu = (const float*)d_in[7];
    const float* Wlv = (const float*)d_in[8];
    const float* blv = (const float*)d_in[9];
    float* out = (float*)d_out;

    const int N = in_sizes[0] / 128;
    const int E = in_sizes[1] / 2;

    cudaFuncSetAttribute(gemm_conv_kernel,
                         cudaFuncAttributeMaxDynamicSharedMemorySize, GEMM_SMEM);
    cudaFuncSetAttribute(gemm_final_kernel,
                         cudaFuncAttributeMaxDynamicSharedMemorySize, GEMM_SMEM);

    const int gemm_blocks = (N + 127) / 128;
    const int scat_blocks = (E + 7) / 8;   // 8 warps/block, 1 warp/edge

    // degrees
    init_one_kernel<<<(N + 255) / 256, 256>>>(N);
    count_deg_kernel<<<(E + 255) / 256, 256>>>(ei, E);
    rsqrt_kernel<<<(N + 255) / 256, 256>>>(N);

    // conv1: x -> hs, aggA ; scatter into aggA
    gemm_conv_kernel<<<gemm_blocks, 512, GEMM_SMEM>>>(x, W1, b1 /*unused*/, N, 0);
    scatter_kernel<<<scat_blocks, 256>>>(ei, E, 0);

    // conv2: relu(dinv*aggA + b1) -> hs, aggB ; scatter into aggB
    gemm_conv_kernel<<<gemm_blocks, 512, GEMM_SMEM>>>(x, W2, b1, N, 1);
    scatter_kernel<<<scat_blocks, 256>>>(ei, E, 1);

    // heads: relu(dinv*aggB + b2) @ [Wmu|Wlv] + [bmu|blv]
    gemm_final_kernel<<<gemm_blocks, 512, GEMM_SMEM>>>(Wmu, Wlv, bmu, blv, b2, out, N);
}

// round 6
// speedup vs baseline: 1.9166x; 1.9166x over previous
#include <cuda_runtime.h>
#include <cuda_bf16.h>
#include <cstdint>

// ---------------------------------------------------------------------------
// GCN VGAE encoder (fp32, f32x2 FFMA GEMMs 64x128 tile, CSR node-centric agg)
//   dinv = rsqrt(indeg+1)
//   conv: hs = (X@W)*dinv[row]
//         agg[v] = hs[v] + sum_{(s->v) in E} hs[s]        (CSR gather, 1 write)
//         next input = relu(dinv[v]*agg[v] + b)           (fused in consumer GEMM)
//   heads: [mu|lv] = relu(dinv*aggB + b2) @ [Wmu|Wlv] + bias
// Scratch = __device__ globals, referenced ONLY from device code.
// ---------------------------------------------------------------------------

#define MAXN 50000
#define MAXE 800000
#define FDIM 128

__device__ float g_dinv[MAXN];
__device__ int   g_degi[MAXN];
__device__ int   g_off [MAXN + 1];
__device__ int   g_cur [MAXN];
__device__ int   g_csr [MAXE];
__device__ int   g_bsum[256];
__device__ float g_hs  [MAXN * FDIM];
__device__ float g_aggA[MAXN * FDIM];
__device__ float g_aggB[MAXN * FDIM];

typedef unsigned long long ull;

#define SPLAT2(d, x) asm("mov.b64 %0, {%1, %1};" : "=l"(d) : "f"(x))
#define FMA2(d, a, b, c) \
    asm("fma.rn.f32x2 %0, %1, %2, %3;" : "=l"(d) : "l"(a), "l"(b), "l"(c))
#define UNPACK2(lo, hi, v) \
    asm("mov.b64 {%0, %1}, %2;" : "=f"(lo), "=f"(hi) : "l"(v))

// ======================= degree + CSR build =======================

__global__ void zero_deg_kernel(int N) {
    int i = blockIdx.x * blockDim.x + threadIdx.x;
    if (i < N) g_degi[i] = 0;
}

__global__ void count_deg_kernel(const int* __restrict__ ei, int E) {
    int e = blockIdx.x * blockDim.x + threadIdx.x;
    if (e < E) atomicAdd(&g_degi[ei[E + e]], 1);
}

// block sums of deg, 256 nodes per block
__global__ void scan1_kernel(int N) {
    __shared__ int s[256];
    int t = threadIdx.x;
    int i = blockIdx.x * 256 + t;
    s[t] = (i < N) ? g_degi[i] : 0;
    __syncthreads();
#pragma unroll
    for (int d = 128; d > 0; d >>= 1) {
        if (t < d) s[t] += s[t + d];
        __syncthreads();
    }
    if (t == 0) g_bsum[blockIdx.x] = s[0];
}

// exclusive scan of up to 256 block sums (single block)
__global__ void scan2_kernel(int nb) {
    __shared__ int s[256];
    int t = threadIdx.x;
    int x = (t < nb) ? g_bsum[t] : 0;
    s[t] = x;
    __syncthreads();
#pragma unroll
    for (int d = 1; d < 256; d <<= 1) {
        int v = (t >= d) ? s[t - d] : 0;
        __syncthreads();
        s[t] += v;
        __syncthreads();
    }
    g_bsum[t] = s[t] - x;   // exclusive
}

// per-block exclusive scan + base; write off, cur, dinv
__global__ void scan3_kernel(int N) {
    __shared__ int s[256];
    int t = threadIdx.x;
    int i = blockIdx.x * 256 + t;
    int deg = (i < N) ? g_degi[i] : 0;
    s[t] = deg;
    __syncthreads();
#pragma unroll
    for (int d = 1; d < 256; d <<= 1) {
        int v = (t >= d) ? s[t - d] : 0;
        __syncthreads();
        s[t] += v;
        __syncthreads();
    }
    if (i < N) {
        int off = g_bsum[blockIdx.x] + s[t] - deg;
        g_off[i] = off;
        g_cur[i] = off;
        g_dinv[i] = rsqrtf((float)deg + 1.0f);
        if (i == N - 1) g_off[N] = off + deg;
    }
}

__global__ void fill_csr_kernel(const int* __restrict__ ei, int E) {
    int e = blockIdx.x * blockDim.x + threadIdx.x;
    if (e < E) {
        int d = ei[E + e];
        int pos = atomicAdd(&g_cur[d], 1);
        g_csr[pos] = ei[e];
    }
}

// ======================= GEMM machinery =======================
// 256 threads, tile 64 rows x 128 cols. tx=t&31 -> cols tx*4..+3 ;
// ty=t>>5 (8 warps) -> rows ty*8..+7. Ws[128][128] + Xs[64][128] = 96KB smem.

#define GEMM_SMEM ((128 * 128 + 64 * 128) * 4)

__device__ __forceinline__ void load_xtile(float* Xs, const float* __restrict__ src,
                                           const float* __restrict__ bias, int fuse,
                                           int rowBase, int N, int t) {
#pragma unroll
    for (int i = 0; i < 8; i++) {
        int idx = t + i * 256;          // 0..2047 float4 slots
        int r = idx >> 5, c4 = idx & 31;
        int rg = rowBase + r;
        float4 v = make_float4(0.f, 0.f, 0.f, 0.f);
        if (rg < N) {
            v = ((const float4*)src)[(size_t)rg * 32 + c4];
            if (fuse) {
                float dv = g_dinv[rg];
                float4 bb = ((const float4*)bias)[c4];
                v.x = fmaxf(v.x * dv + bb.x, 0.f);
                v.y = fmaxf(v.y * dv + bb.y, 0.f);
                v.z = fmaxf(v.z * dv + bb.z, 0.f);
                v.w = fmaxf(v.w * dv + bb.w, 0.f);
            }
        }
        ((float4*)Xs)[idx] = v;
    }
}

// 64x128x128 tile product. 8 rows x 4 cols (2 f32x2) per thread.
__device__ __forceinline__ void mm_tile(const float* Ws, const float* Xs,
                                        int c0, int r0, ull acc[8][2]) {
#pragma unroll
    for (int i = 0; i < 8; i++) { acc[i][0] = 0ull; acc[i][1] = 0ull; }

#pragma unroll 2
    for (int k0 = 0; k0 < 128; k0 += 4) {
        float4 a[8];
#pragma unroll
        for (int i = 0; i < 8; i++)
            a[i] = *(const float4*)(Xs + (r0 + i) * 128 + k0);
#pragma unroll
        for (int kk = 0; kk < 4; kk++) {
            ulonglong2 w = *(const ulonglong2*)(Ws + (k0 + kk) * 128 + c0);
#pragma unroll
            for (int i = 0; i < 8; i++) {
                ull s;
                SPLAT2(s, ((const float*)&a[i])[kk]);
                FMA2(acc[i][0], s, w.x, acc[i][0]);
                FMA2(acc[i][1], s, w.y, acc[i][1]);
            }
        }
    }
}

// conv GEMM: hs = (X@W)*dinv. stage0: X=xin raw; stage1: X=relu(dinv*aggA+bias)
__global__ void __launch_bounds__(256)
gemm_conv_kernel(const float* __restrict__ xin,
                 const float* __restrict__ W,
                 const float* __restrict__ bias,
                 int N, int stage) {
    extern __shared__ float sm[];
    float* Ws = sm;
    float* Xs = sm + 128 * 128;
    const int t = threadIdx.x;
    const float* src = (stage == 0) ? xin : (const float*)g_aggA;

#pragma unroll
    for (int i = 0; i < 16; i++) {
        int idx = t + i * 256;
        ((float4*)Ws)[idx] = ((const float4*)W)[idx];
    }
    const int rowBase = blockIdx.x * 64;
    load_xtile(Xs, src, bias, stage != 0, rowBase, N, t);
    __syncthreads();

    const int tx = t & 31, ty = t >> 5;
    const int c0 = tx * 4, r0 = ty * 8;
    ull acc[8][2];
    mm_tile(Ws, Xs, c0, r0, acc);

#pragma unroll
    for (int i = 0; i < 8; i++) {
        int r = rowBase + r0 + i;
        if (r < N) {
            float dv = g_dinv[r];
            float a0, a1, a2, a3;
            UNPACK2(a0, a1, acc[i][0]);
            UNPACK2(a2, a3, acc[i][1]);
            *(float4*)(g_hs + (size_t)r * 128 + c0) =
                make_float4(a0 * dv, a1 * dv, a2 * dv, a3 * dv);
        }
    }
}

// final GEMM: [mu|lv] = relu(dinv*aggB+b2) @ [Wmu|Wlv] + bias
__global__ void __launch_bounds__(256)
gemm_final_kernel(const float* __restrict__ Wmu,
                  const float* __restrict__ Wlv,
                  const float* __restrict__ bmu,
                  const float* __restrict__ blv,
                  const float* __restrict__ b2,
                  float* __restrict__ out,
                  int N) {
    extern __shared__ float sm[];
    float* Ws = sm;
    float* Xs = sm + 128 * 128;
    const int t = threadIdx.x;

#pragma unroll
    for (int i = 0; i < 16; i++) {
        int idx = t + i * 256;
        int k = idx >> 5;
        int cc4 = idx & 31;
        float4 v = (cc4 < 16) ? ((const float4*)Wmu)[k * 16 + cc4]
                              : ((const float4*)Wlv)[k * 16 + (cc4 - 16)];
        ((float4*)Ws)[idx] = v;
    }
    const int rowBase = blockIdx.x * 64;
    load_xtile(Xs, (const float*)g_aggB, b2, 1, rowBase, N, t);
    __syncthreads();

    const int tx = t & 31, ty = t >> 5;
    const int c0 = tx * 4, r0 = ty * 8;
    ull acc[8][2];
    mm_tile(Ws, Xs, c0, r0, acc);

    const bool is_mu = (c0 < 64);
    const int cl = is_mu ? c0 : (c0 - 64);
    float4 bs = is_mu ? *(const float4*)(bmu + cl) : *(const float4*)(blv + cl);
#pragma unroll
    for (int i = 0; i < 8; i++) {
        int r = rowBase + r0 + i;
        if (r < N) {
            float a0, a1, a2, a3;
            UNPACK2(a0, a1, acc[i][0]);
            UNPACK2(a2, a3, acc[i][1]);
            float* base = is_mu ? (out + (size_t)r * 64 + cl)
                                : (out + (size_t)N * 64 + (size_t)r * 64 + cl);
            *(float4*)base = make_float4(a0 + bs.x, a1 + bs.y, a2 + bs.z, a3 + bs.w);
        }
    }
}

// ============ gather: agg[v] = hs[v] + sum_in-edges hs[src] (warp/node) =====

__global__ void gather_kernel(int N, int which) {
    int node = (blockIdx.x * blockDim.x + threadIdx.x) >> 5;
    int lane = threadIdx.x & 31;
    if (node >= N) return;
    float* agg = which ? g_aggB : g_aggA;

    const float4* hs4 = (const float4*)g_hs;
    float4 acc = hs4[(size_t)node * 32 + lane];   // self-loop seed

    int j = g_off[node];
    int end = g_off[node + 1];
    for (; j + 4 <= end; j += 4) {
        int s0 = g_csr[j], s1 = g_csr[j + 1], s2 = g_csr[j + 2], s3 = g_csr[j + 3];
        float4 v0 = hs4[(size_t)s0 * 32 + lane];
        float4 v1 = hs4[(size_t)s1 * 32 + lane];
        float4 v2 = hs4[(size_t)s2 * 32 + lane];
        float4 v3 = hs4[(size_t)s3 * 32 + lane];
        v0.x += v1.x; v0.y += v1.y; v0.z += v1.z; v0.w += v1.w;
        v2.x += v3.x; v2.y += v3.y; v2.z += v3.z; v2.w += v3.w;
        acc.x += v0.x + v2.x; acc.y += v0.y + v2.y;
        acc.z += v0.z + v2.z; acc.w += v0.w + v2.w;
    }
    for (; j < end; j++) {
        int s = g_csr[j];
        float4 v = hs4[(size_t)s * 32 + lane];
        acc.x += v.x; acc.y += v.y; acc.z += v.z; acc.w += v.w;
    }
    ((float4*)agg)[(size_t)node * 32 + lane] = acc;
}

// ======================= launch =======================

extern "C" void kernel_launch(void* const* d_in, const int* in_sizes, int n_in,
                              void* d_out, int out_size) {
    const float* x   = (const float*)d_in[0];
    const int*   ei  = (const int*)d_in[1];      // int32 edge_index [2, E]
    const float* W1  = (const float*)d_in[2];
    const float* b1  = (const float*)d_in[3];
    const float* W2  = (const float*)d_in[4];
    const float* b2  = (const float*)d_in[5];
    const float* Wmu = (const float*)d_in[6];
    const float* bmu = (const float*)d_in[7];
    const float* Wlv = (const float*)d_in[8];
    const float* blv = (const float*)d_in[9];
    float* out = (float*)d_out;

    const int N = in_sizes[0] / 128;
    const int E = in_sizes[1] / 2;

    cudaFuncSetAttribute(gemm_conv_kernel,
                         cudaFuncAttributeMaxDynamicSharedMemorySize, GEMM_SMEM);
    cudaFuncSetAttribute(gemm_final_kernel,
                         cudaFuncAttributeMaxDynamicSharedMemorySize, GEMM_SMEM);

    const int nb = (N + 255) / 256;               // <= 256 blocks for N <= 65536
    const int gemm_blocks = (N + 63) / 64;
    const int gath_blocks = (N + 7) / 8;          // 8 warps/block, 1 warp/node

    // degree + CSR
    zero_deg_kernel<<<nb, 256>>>(N);
    count_deg_kernel<<<(E + 255) / 256, 256>>>(ei, E);
    scan1_kernel<<<nb, 256>>>(N);
    scan2_kernel<<<1, 256>>>(nb);
    scan3_kernel<<<nb, 256>>>(N);
    fill_csr_kernel<<<(E + 255) / 256, 256>>>(ei, E);

    // conv1: x -> hs ; gather -> aggA
    gemm_conv_kernel<<<gemm_blocks, 256, GEMM_SMEM>>>(x, W1, b1 /*unused*/, N, 0);
    gather_kernel<<<gath_blocks, 256>>>(N, 0);

    // conv2: relu(dinv*aggA + b1) -> hs ; gather -> aggB
    gemm_conv_kernel<<<gemm_blocks, 256, GEMM_SMEM>>>(x, W2, b1, N, 1);
    gather_kernel<<<gath_blocks, 256>>>(N, 1);

    // heads
    gemm_final_kernel<<<gemm_blocks, 256, GEMM_SMEM>>>(Wmu, Wlv, bmu, blv, b2, out, N);
}